// round 8
// baseline (speedup 1.0000x reference)
#include <cuda_runtime.h>
#include <cuda_fp16.h>
#include <cstdint>

// ---------------------------------------------------------------------------
// Problem constants
// ---------------------------------------------------------------------------
#define B_ 2048
#define I_ 2048
#define H_ 2048
#define T_ 4
#define M_ (B_ * T_)   // 8192
#define N_ (3 * H_)    // 6144
#define K_ I_          // 2048

#define DELTA 1.2e-3f
#define FIXCAP (1u << 20)
#define NBIN 1024                          // X-row bins (8 rows each)
#define BINCAP 1024
#define NPLANEW ((size_t)M_ * H_ / 32)     // 524288 words per plane (2 MB)

// Scratch (device globals: allocation-free)
__device__ float  g_Xf[(size_t)M_ * K_];      // 64 MB fp32 transposed inputs (fixup)
__device__ __half g_A16[(size_t)M_ * K_];     // 32 MB fp16 X
__device__ __half g_B16[(size_t)N_ * K_];     // 24 MB fp16 W_ih
__device__ unsigned g_pr[NPLANEW];            // gate bit-planes (2 MB each)
__device__ unsigned g_pz[NPLANEW];
__device__ unsigned g_pn0[NPLANEW];           // n-gate, hypothesis r=0
__device__ unsigned g_pn1[NPLANEW];           // n-gate, hypothesis r=1
__device__ unsigned g_bincnt[NBIN];
__device__ unsigned g_fixbin[(size_t)NBIN * BINCAP];   // 4 MB
__device__ unsigned g_fix[FIXCAP];            // overflow list
__device__ unsigned g_nfix;

// Bit layout: word index = ((row>>3)*256 + ((col&2047)>>3))*2 + (col&1)
//             bit index  = 4*(row&7) + ((col&7)>>1)

// ---------------------------------------------------------------------------
// Helpers
// ---------------------------------------------------------------------------
__device__ __forceinline__ uint32_t smem_u32(const void* p) {
    uint32_t a;
    asm("{ .reg .u64 t; cvta.to.shared.u64 t, %1; cvt.u32.u64 %0, t; }" : "=r"(a) : "l"(p));
    return a;
}
#define SWZ128(o) ((o) ^ (((o) >> 3) & 0x70))

__device__ __forceinline__ void cp_async16(uint32_t s, const void* g) {
    asm volatile("cp.async.cg.shared.global [%0], [%1], 16;" :: "r"(s), "l"(g));
}
#define CP_COMMIT() asm volatile("cp.async.commit_group;" ::: "memory")
#define CP_WAIT(n)  asm volatile("cp.async.wait_group %0;" :: "n"(n) : "memory")

#define LDSM4(r0, r1, r2, r3, addr)                                              \
    asm volatile("ldmatrix.sync.aligned.m8n8.x4.shared.b16 {%0,%1,%2,%3}, [%4];" \
                 : "=r"(r0), "=r"(r1), "=r"(r2), "=r"(r3) : "r"(addr))

#define MMA16816(d, a, b)                                                        \
    asm volatile("mma.sync.aligned.m16n8k16.row.col.f32.f16.f16.f32 "            \
                 "{%0,%1,%2,%3}, {%4,%5,%6,%7}, {%8,%9}, {%0,%1,%2,%3};"         \
                 : "+f"((d)[0]), "+f"((d)[1]), "+f"((d)[2]), "+f"((d)[3])        \
                 : "r"((a)[0]), "r"((a)[1]), "r"((a)[2]), "r"((a)[3]),           \
                   "r"((b)[0]), "r"((b)[1]))

// ---------------------------------------------------------------------------
// zero counters (runs first every launch/replay)
// ---------------------------------------------------------------------------
__global__ void zero_fix_kernel() {
    int t = threadIdx.x;
    if (t < NBIN) g_bincnt[t] = 0u;
    if (t == 0) g_nfix = 0u;
}

// ---------------------------------------------------------------------------
// Prep: transpose inputs -> fp32 X + fp16 X; convert W -> fp16
// ---------------------------------------------------------------------------
__global__ void prep_A(const float* __restrict__ in) {
    int idx = blockIdx.x * blockDim.x + threadIdx.x;   // over B*I
    if (idx >= B_ * I_) return;
    int b = idx / I_;
    int i = idx - b * I_;
    float4 v = *(const float4*)(in + (size_t)idx * T_);
    float vs[4] = {v.x, v.y, v.z, v.w};
#pragma unroll
    for (int t = 0; t < 4; t++) {
        size_t o = (size_t)(b * 4 + t) * K_ + i;
        float a = vs[t];
        g_Xf[o] = a;
        g_A16[o] = __float2half_rn(a);
    }
}

__global__ void prep_B(const float* __restrict__ W) {
    int idx = blockIdx.x * blockDim.x + threadIdx.x;   // over N*K/4
    if (idx >= N_ * K_ / 4) return;
    float4 v = *(const float4*)(W + (size_t)idx * 4);
    __half o0[4];
    o0[0] = __float2half_rn(v.x);
    o0[1] = __float2half_rn(v.y);
    o0[2] = __float2half_rn(v.z);
    o0[3] = __float2half_rn(v.w);
    *(uint2*)&g_B16[(size_t)idx * 4] = *(uint2*)o0;
}

// ---------------------------------------------------------------------------
// Flag push: bin by X-row block (row>>3); overflow to global list.
// ---------------------------------------------------------------------------
__device__ __forceinline__ void push_flag(int row, int col) {
    unsigned ent = ((unsigned)row << 13) | (unsigned)col;
    unsigned bin = (unsigned)row >> 3;
    unsigned idx = atomicAdd(&g_bincnt[bin], 1u);
    if (idx < BINCAP) {
        g_fixbin[(size_t)bin * BINCAP + idx] = ent;
    } else {
        unsigned o = atomicAdd(&g_nfix, 1u);
        if (o < FIXCAP) g_fix[o] = ent;
    }
}

// ---------------------------------------------------------------------------
// HMMA GEMM (single fp16 pass) with bit-plane epilogue.
// CTA tile 128x128, 4 warps (2x2, warp tile 64x64), K-chunk 64,
// 3-stage cp.async pipeline, one __syncthreads per chunk.
// ---------------------------------------------------------------------------
#define NCH 32
#define STAGE_B 32768                       // 16 KB A + 16 KB B
#define NSTAGE 3
#define SMEM_TOTAL (NSTAGE * STAGE_B)       // 96 KB

__device__ __forceinline__ void load_chunk(uint32_t sb, int stage, int c,
                                           int by, int bx, int tid) {
    int kb = c * 64;
    uint32_t stBase = sb + stage * STAGE_B;
#pragma unroll
    for (int q = 0; q < 16; ++q) {
        int sidx = tid + q * 128;          // 0..2047
        int isB = sidx >> 10;
        int within = sidx & 1023;
        int row = within >> 3;
        int seg = within & 7;
        uint32_t off = SWZ128(row * 128 + seg * 16);
        const __half* src = isB
            ? (g_B16 + (size_t)(bx * 128 + row) * K_ + kb + seg * 8)
            : (g_A16 + (size_t)(by * 128 + row) * K_ + kb + seg * 8);
        cp_async16(stBase + isB * 16384 + off, src);
    }
    CP_COMMIT();
}

__global__ __launch_bounds__(128, 2) void gemm_kernel(const float* __restrict__ bih,
                                                      const float* __restrict__ bhh) {
    extern __shared__ __align__(128) char smem[];
    uint32_t sb = smem_u32(smem);
    const int tid = threadIdx.x;
    const int wid = tid >> 5;
    const int lid = tid & 31;
    const int bx = blockIdx.x;    // N tile (48)
    const int by = blockIdx.y;    // M tile (64)
    const int warp_m = wid >> 1;  // 0..1
    const int warp_n = wid & 1;   // 0..1
    const int grp = lid >> 3, lrow = lid & 7;

    float acc[4][8][4] = {};      // m16-frag x n8-frag x regs

    load_chunk(sb, 0, 0, by, bx, tid);
    load_chunk(sb, 1, 1, by, bx, tid);

    int s_cur = 0;
    for (int c = 0; c < NCH; ++c) {
        if (c + 1 < NCH) { CP_WAIT(1); } else { CP_WAIT(0); }
        __syncthreads();
        if (c + 2 < NCH) {
            int ns = s_cur + 2; if (ns >= NSTAGE) ns -= NSTAGE;
            load_chunk(sb, ns, c + 2, by, bx, tid);
        }

        uint32_t sA = sb + s_cur * STAGE_B;
        uint32_t sB = sA + 16384;
#pragma unroll
        for (int ks = 0; ks < 4; ++ks) {
            uint32_t Af[4][4];
#pragma unroll
            for (int am = 0; am < 4; ++am) {
                int row = warp_m * 64 + am * 16 + (grp & 1) * 8 + lrow;
                uint32_t ad = sA + SWZ128(row * 128 + ks * 32 + (grp >> 1) * 16);
                LDSM4(Af[am][0], Af[am][1], Af[am][2], Af[am][3], ad);
            }
            uint32_t Bf[8][2];
#pragma unroll
            for (int bp = 0; bp < 4; ++bp) {
                int row = warp_n * 64 + bp * 16 + (grp >> 1) * 8 + lrow;
                uint32_t ad = sB + SWZ128(row * 128 + ks * 32 + (grp & 1) * 16);
                uint32_t r0, r1, r2, r3;
                LDSM4(r0, r1, r2, r3, ad);
                Bf[bp * 2][0] = r0; Bf[bp * 2][1] = r1;
                Bf[bp * 2 + 1][0] = r2; Bf[bp * 2 + 1][1] = r3;
            }
#pragma unroll
            for (int am = 0; am < 4; ++am)
#pragma unroll
                for (int bn = 0; bn < 8; ++bn)
                    MMA16816(acc[am][bn], Af[am], Bf[bn]);
        }
        ++s_cur; if (s_cur >= NSTAGE) s_cur = 0;
    }

    // Epilogue: resolve gates to bit-planes + borderline flagging
#pragma unroll
    for (int bn = 0; bn < 8; ++bn) {
        int colb = bx * 128 + warp_n * 64 + bn * 8;   // 8-col block base
        int col = colb + (lid & 3) * 2;
        float bih0 = bih[col], bih1 = bih[col + 1];
        float bhh0 = bhh[col], bhh1 = bhh[col + 1];
        int gate = colb >> 11;                        // 0:r 1:z 2:n
        float t2a = bih0 + bhh0, t2b = bih1 + bhh1;
        float t1a = bih0, t1b = bih1;                 // n-gate r=0 hypothesis
        unsigned blkc = (unsigned)((colb & 2047) >> 3);
#pragma unroll
        for (int am = 0; am < 4; ++am) {
#pragma unroll
            for (int half = 0; half < 2; ++half) {
                int row8 = by * 128 + warp_m * 64 + am * 16 + half * 8;
                float y0 = acc[am][bn][half * 2 + 0];
                float y1 = acc[am][bn][half * 2 + 1];
                unsigned mE = __ballot_sync(0xFFFFFFFFu, (y0 + t2a) > 0.0f);
                unsigned mO = __ballot_sync(0xFFFFFFFFu, (y1 + t2b) > 0.0f);
                unsigned wi = ((unsigned)(row8 >> 3) * 256u + blkc) * 2u;
                if (gate == 2) {
                    unsigned mE0 = __ballot_sync(0xFFFFFFFFu, (y0 + t1a) > 0.0f);
                    unsigned mO0 = __ballot_sync(0xFFFFFFFFu, (y1 + t1b) > 0.0f);
                    if (lid == 0) {
                        g_pn1[wi] = mE; g_pn1[wi + 1] = mO;
                        g_pn0[wi] = mE0; g_pn0[wi + 1] = mO0;
                    }
                } else {
                    unsigned* pl = gate ? g_pz : g_pr;
                    if (lid == 0) { pl[wi] = mE; pl[wi + 1] = mO; }
                }
                int row = row8 + (lid >> 2);
                bool f0 = fabsf(y0 + t2a) < DELTA ||
                          (gate == 2 && fabsf(y0 + t1a) < DELTA);
                bool f1 = fabsf(y1 + t2b) < DELTA ||
                          (gate == 2 && fabsf(y1 + t1b) < DELTA);
                if (f0) push_flag(row, col);
                if (f1) push_flag(row, col + 1);
            }
        }
    }
}

// ---------------------------------------------------------------------------
// Exact recompute body (TwoProd + Kahan fp32, fp64 lane merge) + bit fix.
// IDENTICAL arithmetic to the proven round-6 fixup.
// ---------------------------------------------------------------------------
__device__ __forceinline__ void fix_entry(unsigned ent, int lid,
                                          const float* __restrict__ W,
                                          const float* __restrict__ bih,
                                          const float* __restrict__ bhh) {
    int m = ent >> 13;
    int c = ent & 0x1FFF;
    const float* xr = g_Xf + (size_t)m * K_;
    const float* wr = W + (size_t)c * K_;
    float s = 0.0f, comp = 0.0f, es = 0.0f;
#pragma unroll
    for (int i = 0; i < 16; ++i) {
        int k = (i * 32 + lid) * 4;
        float4 x = *(const float4*)(xr + k);
        float4 w = *(const float4*)(wr + k);
        const float xs[4] = {x.x, x.y, x.z, x.w};
        const float ws[4] = {w.x, w.y, w.z, w.w};
#pragma unroll
        for (int j = 0; j < 4; ++j) {
            float p  = __fmul_rn(xs[j], ws[j]);
            float lo = __fmaf_rn(xs[j], ws[j], -p);
            float y = __fsub_rn(p, comp);
            float t = __fadd_rn(s, y);
            comp = __fsub_rn(__fsub_rn(t, s), y);
            s = t;
            es = __fadd_rn(es, lo);
        }
    }
    double v = (double)s - (double)comp + (double)es;
#pragma unroll
    for (int off = 16; off > 0; off >>= 1)
        v += __shfl_down_sync(0xFFFFFFFFu, v, off);
    if (lid == 0) {
        float vf = (float)v;
        int gate = c >> 11;
        unsigned wi = (((unsigned)(m >> 3)) * 256u + (unsigned)((c & 2047) >> 3)) * 2u
                      + (unsigned)(c & 1);
        unsigned bit = 1u << (4 * (m & 7) + ((c & 7) >> 1));
        if (gate < 2) {
            bool bv = ((vf + bih[c]) + bhh[c]) > 0.0f;
            unsigned* pl = gate ? g_pz : g_pr;
            if (bv) atomicOr(&pl[wi], bit); else atomicAnd(&pl[wi], ~bit);
        } else {
            bool b0 = (vf + bih[c]) > 0.0f;
            bool b1 = ((vf + bih[c]) + bhh[c]) > 0.0f;
            if (b0) atomicOr(&g_pn0[wi], bit); else atomicAnd(&g_pn0[wi], ~bit);
            if (b1) atomicOr(&g_pn1[wi], bit); else atomicAnd(&g_pn1[wi], ~bit);
        }
    }
}

// Binned fixup: one block per bin; its 8 X-rows stay hot in L1/L2.
__global__ void fixup_binned(const float* __restrict__ W,
                             const float* __restrict__ bih,
                             const float* __restrict__ bhh) {
    int bin = blockIdx.x;
    int wib = threadIdx.x >> 5;
    int lid = threadIdx.x & 31;
    unsigned cnt = g_bincnt[bin];
    if (cnt > BINCAP) cnt = BINCAP;
    for (unsigned e = wib; e < cnt; e += 8)
        fix_entry(g_fixbin[(size_t)bin * BINCAP + e], lid, W, bih, bhh);
}

// Overflow fixup (normally empty)
__global__ void fixup_overflow(const float* __restrict__ W,
                               const float* __restrict__ bih,
                               const float* __restrict__ bhh) {
    int gw = (blockIdx.x * blockDim.x + threadIdx.x) >> 5;
    int lid = threadIdx.x & 31;
    int nwarps = (gridDim.x * blockDim.x) >> 5;
    unsigned n = g_nfix;
    if (n > FIXCAP) n = FIXCAP;
    for (unsigned e = gw; e < n; e += nwarps)
        fix_entry(g_fix[e], lid, W, bih, bhh);
}

// ---------------------------------------------------------------------------
// LIF from bit-planes. One thread per (b, h).
// ---------------------------------------------------------------------------
__global__ void lif_kernel(float* __restrict__ out) {
    int idx = blockIdx.x * blockDim.x + threadIdx.x;   // over B*H
    if (idx >= B_ * H_) return;
    int b = idx >> 11;
    int h = idx & 2047;

    unsigned wi = (((unsigned)(b >> 1)) * 256u + (unsigned)(h >> 3)) * 2u
                  + (unsigned)(h & 1);
    int s0 = ((b & 1) << 4) + ((h & 7) >> 1);

    unsigned wr = g_pr[wi];
    unsigned wz = g_pz[wi];
    unsigned w0 = g_pn0[wi];
    unsigned w1 = g_pn1[wi];

    float mem = 0.0f;
    float4 spk4;
    float* sp = &spk4.x;

#pragma unroll
    for (int t = 0; t < T_; t++) {
        int sh = s0 + (t << 2);
        unsigned rb = (wr >> sh) & 1u;
        unsigned zb = (wz >> sh) & 1u;
        unsigned nb = rb ? ((w1 >> sh) & 1u) : ((w0 >> sh) & 1u);
        float h_t = zb ? 0.0f : (float)nb;

        float reset = (mem - 1.0f) > 0.0f ? 1.0f : 0.0f;
        mem = 0.99f * mem + h_t - reset * 1.0f;
        sp[t] = (mem - 1.0f) > 0.0f ? 1.0f : 0.0f;
    }

    *(float4*)(out + (size_t)idx * T_) = spk4;
}

// ---------------------------------------------------------------------------
extern "C" void kernel_launch(void* const* d_in, const int* in_sizes, int n_in,
                              void* d_out, int out_size) {
    const float* inp = (const float*)d_in[0];   // inputs [B, I, T]
    const float* Wih = (const float*)d_in[1];   // [3H, I]
    const float* bih = (const float*)d_in[2];   // [3H]
    // d_in[3] = W_hh unused (h0 == 0)
    const float* bhh = (const float*)d_in[4];   // [3H]
    float* out = (float*)d_out;                 // [B, H, T]

    cudaFuncSetAttribute(gemm_kernel, cudaFuncAttributeMaxDynamicSharedMemorySize,
                         SMEM_TOTAL);

    zero_fix_kernel<<<1, NBIN>>>();
    prep_A<<<(B_ * I_ + 255) / 256, 256>>>(inp);
    prep_B<<<(N_ * K_ / 4 + 255) / 256, 256>>>(Wih);

    dim3 grid(N_ / 128, M_ / 128);   // (48, 64)
    gemm_kernel<<<grid, 128, SMEM_TOTAL>>>(bih, bhh);

    fixup_binned<<<NBIN, 256>>>(Wih, bih, bhh);
    fixup_overflow<<<64, 256>>>(Wih, bih, bhh);
    lif_kernel<<<(B_ * H_ + 255) / 256, 256>>>(out);
}

// round 9
// speedup vs baseline: 1.2334x; 1.2334x over previous
#include <cuda_runtime.h>
#include <cuda_fp16.h>
#include <cstdint>

// ---------------------------------------------------------------------------
// Problem constants
// ---------------------------------------------------------------------------
#define B_ 2048
#define I_ 2048
#define H_ 2048
#define T_ 4
#define M_ (B_ * T_)   // 8192
#define N_ (3 * H_)    // 6144
#define K_ I_          // 2048

#define DELTA 1.0e-3f
#define FIXCAP (1u << 20)
#define NBIN 768                           // column bins (8 cols each)
#define BINCAP 1024
#define NPLANEW ((size_t)M_ * H_ / 32)     // 524288 words per plane (2 MB)

// Scratch (device globals: allocation-free)
__device__ float  g_Xf[(size_t)M_ * K_];      // 64 MB fp32 transposed inputs (fixup)
__device__ __half g_A16[(size_t)M_ * K_];     // 32 MB fp16 X
__device__ __half g_B16[(size_t)N_ * K_];     // 24 MB fp16 W_ih
__device__ unsigned g_pr[NPLANEW];            // gate bit-planes (2 MB each)
__device__ unsigned g_pz[NPLANEW];
__device__ unsigned g_pn0[NPLANEW];           // n-gate, hypothesis r=0
__device__ unsigned g_pn1[NPLANEW];           // n-gate, hypothesis r=1
__device__ unsigned g_bincnt[NBIN];
__device__ unsigned g_fixbin[(size_t)NBIN * BINCAP];
__device__ unsigned g_fix[FIXCAP];            // overflow list
__device__ unsigned g_nfix;

// Bit layout: word index = ((row>>3)*256 + ((col&2047)>>3))*2 + (col&1)
//             bit index  = 4*(row&7) + ((col&7)>>1)

// ---------------------------------------------------------------------------
// Helpers
// ---------------------------------------------------------------------------
__device__ __forceinline__ uint32_t smem_u32(const void* p) {
    uint32_t a;
    asm("{ .reg .u64 t; cvta.to.shared.u64 t, %1; cvt.u32.u64 %0, t; }" : "=r"(a) : "l"(p));
    return a;
}
#define SWZ128(o) ((o) ^ (((o) >> 3) & 0x70))

__device__ __forceinline__ void cp_async16(uint32_t s, const void* g) {
    asm volatile("cp.async.cg.shared.global [%0], [%1], 16;" :: "r"(s), "l"(g));
}
#define CP_COMMIT() asm volatile("cp.async.commit_group;" ::: "memory")
#define CP_WAIT(n)  asm volatile("cp.async.wait_group %0;" :: "n"(n) : "memory")

#define LDSM4(r0, r1, r2, r3, addr)                                              \
    asm volatile("ldmatrix.sync.aligned.m8n8.x4.shared.b16 {%0,%1,%2,%3}, [%4];" \
                 : "=r"(r0), "=r"(r1), "=r"(r2), "=r"(r3) : "r"(addr))

#define MMA16816(d, a, b)                                                        \
    asm volatile("mma.sync.aligned.m16n8k16.row.col.f32.f16.f16.f32 "            \
                 "{%0,%1,%2,%3}, {%4,%5,%6,%7}, {%8,%9}, {%0,%1,%2,%3};"         \
                 : "+f"((d)[0]), "+f"((d)[1]), "+f"((d)[2]), "+f"((d)[3])        \
                 : "r"((a)[0]), "r"((a)[1]), "r"((a)[2]), "r"((a)[3]),           \
                   "r"((b)[0]), "r"((b)[1]))

// ---------------------------------------------------------------------------
// zero counters (runs first every launch/replay)
// ---------------------------------------------------------------------------
__global__ void zero_fix_kernel() {
    int t = threadIdx.x;
    if (t < NBIN) g_bincnt[t] = 0u;
    if (t == 0) g_nfix = 0u;
}

// ---------------------------------------------------------------------------
// Prep: transpose inputs -> fp32 X + fp16 X; convert W -> fp16
// ---------------------------------------------------------------------------
__global__ void prep_A(const float* __restrict__ in) {
    int idx = blockIdx.x * blockDim.x + threadIdx.x;   // over B*I
    if (idx >= B_ * I_) return;
    int b = idx / I_;
    int i = idx - b * I_;
    float4 v = *(const float4*)(in + (size_t)idx * T_);
    float vs[4] = {v.x, v.y, v.z, v.w};
#pragma unroll
    for (int t = 0; t < 4; t++) {
        size_t o = (size_t)(b * 4 + t) * K_ + i;
        float a = vs[t];
        g_Xf[o] = a;
        g_A16[o] = __float2half_rn(a);
    }
}

__global__ void prep_B(const float* __restrict__ W) {
    int idx = blockIdx.x * blockDim.x + threadIdx.x;   // over N*K/4
    if (idx >= N_ * K_ / 4) return;
    float4 v = *(const float4*)(W + (size_t)idx * 4);
    __half o0[4];
    o0[0] = __float2half_rn(v.x);
    o0[1] = __float2half_rn(v.y);
    o0[2] = __float2half_rn(v.z);
    o0[3] = __float2half_rn(v.w);
    *(uint2*)&g_B16[(size_t)idx * 4] = *(uint2*)o0;
}

// ---------------------------------------------------------------------------
// Flag push: bin by W-column block (col>>3); overflow to global list.
// ---------------------------------------------------------------------------
__device__ __forceinline__ void push_flag(int row, int col) {
    unsigned ent = ((unsigned)row << 13) | (unsigned)col;
    unsigned bin = (unsigned)col >> 3;
    unsigned idx = atomicAdd(&g_bincnt[bin], 1u);
    if (idx < BINCAP) {
        g_fixbin[(size_t)bin * BINCAP + idx] = ent;
    } else {
        unsigned o = atomicAdd(&g_nfix, 1u);
        if (o < FIXCAP) g_fix[o] = ent;
    }
}

// ---------------------------------------------------------------------------
// HMMA GEMM (single fp16 pass) with bit-plane epilogue.
// CTA tile 128x128, 8 warps (2x4, warp tile 64x32), K-chunk 64,
// 3-stage cp.async pipeline, one __syncthreads per chunk.  (Round-7 proven.)
// ---------------------------------------------------------------------------
#define NCH 32
#define STAGE_B 32768                       // 16 KB A + 16 KB B
#define NSTAGE 3
#define SMEM_TOTAL (NSTAGE * STAGE_B)       // 96 KB

__device__ __forceinline__ void load_chunk(uint32_t sb, int stage, int c,
                                           int by, int bx, int tid) {
    int kb = c * 64;
    uint32_t sA = sb + stage * STAGE_B;
    uint32_t sB = sA + 16384;
#pragma unroll
    for (int q = 0; q < 4; ++q) {
        int sidx = tid + q * 256;      // 0..1023
        int row = sidx >> 3;
        int seg = sidx & 7;
        uint32_t off = SWZ128(row * 128 + seg * 16);
        cp_async16(sA + off, g_A16 + (size_t)(by * 128 + row) * K_ + kb + seg * 8);
        cp_async16(sB + off, g_B16 + (size_t)(bx * 128 + row) * K_ + kb + seg * 8);
    }
    CP_COMMIT();
}

__global__ __launch_bounds__(256, 2) void gemm_kernel(const float* __restrict__ bih,
                                                      const float* __restrict__ bhh) {
    extern __shared__ __align__(128) char smem[];
    uint32_t sb = smem_u32(smem);
    const int tid = threadIdx.x;
    const int wid = tid >> 5;
    const int lid = tid & 31;
    const int bx = blockIdx.x;    // N tile (48)
    const int by = blockIdx.y;    // M tile (64)
    const int warp_m = wid >> 2;  // 0..1
    const int warp_n = wid & 3;   // 0..3
    const int grp = lid >> 3, lrow = lid & 7;

    float acc[4][4][4] = {};

    load_chunk(sb, 0, 0, by, bx, tid);
    load_chunk(sb, 1, 1, by, bx, tid);

    int s_cur = 0;
    for (int c = 0; c < NCH; ++c) {
        if (c + 1 < NCH) { CP_WAIT(1); } else { CP_WAIT(0); }
        __syncthreads();
        if (c + 2 < NCH) {
            int ns = s_cur + 2; if (ns >= NSTAGE) ns -= NSTAGE;
            load_chunk(sb, ns, c + 2, by, bx, tid);
        }

        uint32_t sA = sb + s_cur * STAGE_B;
        uint32_t sB = sA + 16384;
#pragma unroll
        for (int ks = 0; ks < 4; ++ks) {
            uint32_t Af[4][4];
#pragma unroll
            for (int am = 0; am < 4; ++am) {
                int row = warp_m * 64 + am * 16 + (grp & 1) * 8 + lrow;
                uint32_t ad = sA + SWZ128(row * 128 + ks * 32 + (grp >> 1) * 16);
                LDSM4(Af[am][0], Af[am][1], Af[am][2], Af[am][3], ad);
            }
            uint32_t Bf[4][2];
#pragma unroll
            for (int bp = 0; bp < 2; ++bp) {
                int row = warp_n * 32 + bp * 16 + (grp >> 1) * 8 + lrow;
                uint32_t ad = sB + SWZ128(row * 128 + ks * 32 + (grp & 1) * 16);
                uint32_t r0, r1, r2, r3;
                LDSM4(r0, r1, r2, r3, ad);
                Bf[bp * 2][0] = r0; Bf[bp * 2][1] = r1;
                Bf[bp * 2 + 1][0] = r2; Bf[bp * 2 + 1][1] = r3;
            }
#pragma unroll
            for (int am = 0; am < 4; ++am)
#pragma unroll
                for (int bn = 0; bn < 4; ++bn)
                    MMA16816(acc[am][bn], Af[am], Bf[bn]);
        }
        ++s_cur; if (s_cur >= NSTAGE) s_cur = 0;
    }

    // Epilogue: resolve gates to bit-planes + borderline flagging
#pragma unroll
    for (int bn = 0; bn < 4; ++bn) {
        int colb = bx * 128 + warp_n * 32 + bn * 8;   // 8-col block base
        int col = colb + (lid & 3) * 2;
        float bih0 = bih[col], bih1 = bih[col + 1];
        float bhh0 = bhh[col], bhh1 = bhh[col + 1];
        int gate = colb >> 11;                        // 0:r 1:z 2:n
        float t2a = bih0 + bhh0, t2b = bih1 + bhh1;
        float t1a = bih0, t1b = bih1;                 // n-gate r=0 hypothesis
        unsigned blkc = (unsigned)((colb & 2047) >> 3);
#pragma unroll
        for (int am = 0; am < 4; ++am) {
#pragma unroll
            for (int half = 0; half < 2; ++half) {
                int row8 = by * 128 + warp_m * 64 + am * 16 + half * 8;
                float y0 = acc[am][bn][half * 2 + 0];
                float y1 = acc[am][bn][half * 2 + 1];
                unsigned mE = __ballot_sync(0xFFFFFFFFu, (y0 + t2a) > 0.0f);
                unsigned mO = __ballot_sync(0xFFFFFFFFu, (y1 + t2b) > 0.0f);
                unsigned wi = ((unsigned)(row8 >> 3) * 256u + blkc) * 2u;
                if (gate == 2) {
                    unsigned mE0 = __ballot_sync(0xFFFFFFFFu, (y0 + t1a) > 0.0f);
                    unsigned mO0 = __ballot_sync(0xFFFFFFFFu, (y1 + t1b) > 0.0f);
                    if (lid == 0) {
                        g_pn1[wi] = mE; g_pn1[wi + 1] = mO;
                        g_pn0[wi] = mE0; g_pn0[wi + 1] = mO0;
                    }
                } else {
                    unsigned* pl = gate ? g_pz : g_pr;
                    if (lid == 0) { pl[wi] = mE; pl[wi + 1] = mO; }
                }
                int row = row8 + (lid >> 2);
                bool f0 = fabsf(y0 + t2a) < DELTA ||
                          (gate == 2 && fabsf(y0 + t1a) < DELTA);
                bool f1 = fabsf(y1 + t2b) < DELTA ||
                          (gate == 2 && fabsf(y1 + t1b) < DELTA);
                if (f0) push_flag(row, col);
                if (f1) push_flag(row, col + 1);
            }
        }
    }
}

// ---------------------------------------------------------------------------
// Exact recompute body (TwoProd + Kahan fp32, fp64 lane merge) + bit fix.
// IDENTICAL arithmetic to the proven round-6 fixup.
// ---------------------------------------------------------------------------
__device__ __forceinline__ void fix_entry(unsigned ent, int lid,
                                          const float* __restrict__ W,
                                          const float* __restrict__ bih,
                                          const float* __restrict__ bhh) {
    int m = ent >> 13;
    int c = ent & 0x1FFF;
    const float* xr = g_Xf + (size_t)m * K_;
    const float* wr = W + (size_t)c * K_;
    float s = 0.0f, comp = 0.0f, es = 0.0f;
#pragma unroll
    for (int i = 0; i < 16; ++i) {
        int k = (i * 32 + lid) * 4;
        float4 x = *(const float4*)(xr + k);
        float4 w = *(const float4*)(wr + k);
        const float xs[4] = {x.x, x.y, x.z, x.w};
        const float ws[4] = {w.x, w.y, w.z, w.w};
#pragma unroll
        for (int j = 0; j < 4; ++j) {
            float p  = __fmul_rn(xs[j], ws[j]);
            float lo = __fmaf_rn(xs[j], ws[j], -p);
            float y = __fsub_rn(p, comp);
            float t = __fadd_rn(s, y);
            comp = __fsub_rn(__fsub_rn(t, s), y);
            s = t;
            es = __fadd_rn(es, lo);
        }
    }
    double v = (double)s - (double)comp + (double)es;
#pragma unroll
    for (int off = 16; off > 0; off >>= 1)
        v += __shfl_down_sync(0xFFFFFFFFu, v, off);
    if (lid == 0) {
        float vf = (float)v;
        int gate = c >> 11;
        unsigned wi = (((unsigned)(m >> 3)) * 256u + (unsigned)((c & 2047) >> 3)) * 2u
                      + (unsigned)(c & 1);
        unsigned bit = 1u << (4 * (m & 7) + ((c & 7) >> 1));
        if (gate < 2) {
            bool bv = ((vf + bih[c]) + bhh[c]) > 0.0f;
            unsigned* pl = gate ? g_pz : g_pr;
            if (bv) atomicOr(&pl[wi], bit); else atomicAnd(&pl[wi], ~bit);
        } else {
            bool b0 = (vf + bih[c]) > 0.0f;
            bool b1 = ((vf + bih[c]) + bhh[c]) > 0.0f;
            if (b0) atomicOr(&g_pn0[wi], bit); else atomicAnd(&g_pn0[wi], ~bit);
            if (b1) atomicOr(&g_pn1[wi], bit); else atomicAnd(&g_pn1[wi], ~bit);
        }
    }
}

// Binned fixup: one block per column bin; its 8 W-rows stay hot in L1.
__global__ void fixup_binned(const float* __restrict__ W,
                             const float* __restrict__ bih,
                             const float* __restrict__ bhh) {
    int bin = blockIdx.x;
    int wib = threadIdx.x >> 5;
    int lid = threadIdx.x & 31;
    unsigned cnt = g_bincnt[bin];
    if (cnt > BINCAP) cnt = BINCAP;
    for (unsigned e = wib; e < cnt; e += 8)
        fix_entry(g_fixbin[(size_t)bin * BINCAP + e], lid, W, bih, bhh);
}

// Overflow fixup (normally empty)
__global__ void fixup_overflow(const float* __restrict__ W,
                               const float* __restrict__ bih,
                               const float* __restrict__ bhh) {
    int gw = (blockIdx.x * blockDim.x + threadIdx.x) >> 5;
    int lid = threadIdx.x & 31;
    int nwarps = (gridDim.x * blockDim.x) >> 5;
    unsigned n = g_nfix;
    if (n > FIXCAP) n = FIXCAP;
    for (unsigned e = gw; e < n; e += nwarps)
        fix_entry(g_fix[e], lid, W, bih, bhh);
}

// ---------------------------------------------------------------------------
// LIF from bit-planes. One thread per (b, h).
// ---------------------------------------------------------------------------
__global__ void lif_kernel(float* __restrict__ out) {
    int idx = blockIdx.x * blockDim.x + threadIdx.x;   // over B*H
    if (idx >= B_ * H_) return;
    int b = idx >> 11;
    int h = idx & 2047;

    unsigned wi = (((unsigned)(b >> 1)) * 256u + (unsigned)(h >> 3)) * 2u
                  + (unsigned)(h & 1);
    int s0 = ((b & 1) << 4) + ((h & 7) >> 1);

    unsigned wr = g_pr[wi];
    unsigned wz = g_pz[wi];
    unsigned w0 = g_pn0[wi];
    unsigned w1 = g_pn1[wi];

    float mem = 0.0f;
    float4 spk4;
    float* sp = &spk4.x;

#pragma unroll
    for (int t = 0; t < T_; t++) {
        int sh = s0 + (t << 2);
        unsigned rb = (wr >> sh) & 1u;
        unsigned zb = (wz >> sh) & 1u;
        unsigned nb = rb ? ((w1 >> sh) & 1u) : ((w0 >> sh) & 1u);
        float h_t = zb ? 0.0f : (float)nb;

        float reset = (mem - 1.0f) > 0.0f ? 1.0f : 0.0f;
        mem = 0.99f * mem + h_t - reset * 1.0f;
        sp[t] = (mem - 1.0f) > 0.0f ? 1.0f : 0.0f;
    }

    *(float4*)(out + (size_t)idx * T_) = spk4;
}

// ---------------------------------------------------------------------------
extern "C" void kernel_launch(void* const* d_in, const int* in_sizes, int n_in,
                              void* d_out, int out_size) {
    const float* inp = (const float*)d_in[0];   // inputs [B, I, T]
    const float* Wih = (const float*)d_in[1];   // [3H, I]
    const float* bih = (const float*)d_in[2];   // [3H]
    // d_in[3] = W_hh unused (h0 == 0)
    const float* bhh = (const float*)d_in[4];   // [3H]
    float* out = (float*)d_out;                 // [B, H, T]

    cudaFuncSetAttribute(gemm_kernel, cudaFuncAttributeMaxDynamicSharedMemorySize,
                         SMEM_TOTAL);

    zero_fix_kernel<<<1, NBIN>>>();
    prep_A<<<(B_ * I_ + 255) / 256, 256>>>(inp);
    prep_B<<<(N_ * K_ / 4 + 255) / 256, 256>>>(Wih);

    dim3 grid(N_ / 128, M_ / 128);   // (48, 64)
    gemm_kernel<<<grid, 256, SMEM_TOTAL>>>(bih, bhh);

    fixup_binned<<<NBIN, 256>>>(Wih, bih, bhh);
    fixup_overflow<<<64, 256>>>(Wih, bih, bhh);
    lif_kernel<<<(B_ * H_ + 255) / 256, 256>>>(out);
}